// round 3
// baseline (speedup 1.0000x reference)
#include <cuda_runtime.h>
#include <cuda_bf16.h>

// EMA over t: y_0 = x_0, y_t = (1-a)*y_{t-1} + a*x_t, a = 0.3
// Shape (B=8, T=4096, C=1024) fp32, contiguous.
//
// Strategy: chunk the serial t-scan into independent tiles of TCH steps.
// Each tile warms up from t0-LW with seed y = x[t0-LW]; the seed error is
// attenuated by 0.7^LW ~= 3.7e-8 by the time the stored region begins.
// This makes the scan embarrassingly parallel at ~19% extra read traffic.

namespace {
constexpr int T_ = 4096;
constexpr int C_ = 1024;
constexpr float ALPHA = 0.3f;
constexpr float OMA   = 0.7f;   // 1 - alpha

constexpr int TCH    = 256;     // time steps stored per block
constexpr int LW     = 48;      // warm-up steps (0.7^48 ~ 3.7e-8)
constexpr int CSPLIT = 2;       // channel blocks
constexpr int THREADS = (C_ / CSPLIT) / 4;  // 128 threads, one float4 each
constexpr int STRIDE4 = C_ / 4;             // float4 stride per time step
}

__device__ __forceinline__ float4 ema_step(float4 acc, float4 v) {
    float4 r;
    r.x = fmaf(OMA, acc.x, ALPHA * v.x);
    r.y = fmaf(OMA, acc.y, ALPHA * v.y);
    r.z = fmaf(OMA, acc.z, ALPHA * v.z);
    r.w = fmaf(OMA, acc.w, ALPHA * v.w);
    return r;
}

__global__ __launch_bounds__(THREADS)
void ema_kernel(const float* __restrict__ x, float* __restrict__ y) {
    const int c4 = blockIdx.x * THREADS + threadIdx.x;  // float4 index in channel dim
    const int t0 = blockIdx.y * TCH;
    const int b  = blockIdx.z;

    const float4* __restrict__ xv =
        reinterpret_cast<const float4*>(x) + (size_t)b * T_ * STRIDE4 + c4;
    float4* __restrict__ yv =
        reinterpret_cast<float4*>(y) + (size_t)b * T_ * STRIDE4 + c4;

    int ts = t0 - LW;
    if (ts < 0) ts = 0;

    // Seed. For the first chunk this is exact (y_0 = x_0).
    float4 acc = xv[(size_t)ts * STRIDE4];

    int tstart;
    if (t0 == 0) {
        yv[0] = acc;          // y_0 = x_0 exactly
        tstart = 1;
    } else {
        // Warm-up: t = ts+1 .. t0-1, no stores. 47 iterations; unroll-8 lets
        // ptxas front-batch the loads within each group.
        #pragma unroll 8
        for (int t = ts + 1; t < t0; ++t) {
            acc = ema_step(acc, xv[(size_t)t * STRIDE4]);
        }
        tstart = t0;
    }

    // Main stored region: batch 8 time steps so 8 float4 loads are in flight
    // per thread before the dependent FMA chain consumes them.
    const int tend = t0 + TCH;
    int t = tstart;
    for (; t + 8 <= tend; t += 8) {
        float4 v[8];
        #pragma unroll
        for (int i = 0; i < 8; ++i)
            v[i] = xv[(size_t)(t + i) * STRIDE4];
        #pragma unroll
        for (int i = 0; i < 8; ++i) {
            acc = ema_step(acc, v[i]);
            yv[(size_t)(t + i) * STRIDE4] = acc;
        }
    }
    for (; t < tend; ++t) {
        acc = ema_step(acc, xv[(size_t)t * STRIDE4]);
        yv[(size_t)t * STRIDE4] = acc;
    }
}

extern "C" void kernel_launch(void* const* d_in, const int* in_sizes, int n_in,
                              void* d_out, int out_size) {
    const float* x = (const float*)d_in[0];
    float* y = (float*)d_out;
    (void)n_in; (void)out_size;

    const int batch = in_sizes[0] / (T_ * C_);   // 8 for the reference shape
    dim3 grid(CSPLIT, T_ / TCH, batch);          // (2, 16, 8) = 256 blocks
    ema_kernel<<<grid, THREADS>>>(x, y);
}

// round 5
// speedup vs baseline: 1.3262x; 1.3262x over previous
#include <cuda_runtime.h>
#include <cuda_bf16.h>

// EMA over t: y_0 = x_0, y_t = (1-a)*y_{t-1} + a*x_t, a = 0.3
// Shape (B=8, T=4096, C=1024) fp32, contiguous.
//
// Tiled-scan with truncated warm-up (0.7^48 ~ 3.7e-8 seed attenuation).
// R3 ncu: DRAM 43.7%, occ 10.6% -> latency-limited. This round: 4x the warp
// count (float2 lanes + TCH=128) to cover memory latency with warp-level
// parallelism. Traffic: 128MB*(1+48/128) reads + 128MB writes = 304 MB.

namespace {
constexpr int T_ = 4096;
constexpr int C_ = 1024;
constexpr float ALPHA = 0.3f;
constexpr float OMA   = 0.7f;   // 1 - alpha

constexpr int TCH    = 128;     // time steps stored per block
constexpr int LW     = 48;      // warm-up steps
constexpr int CSPLIT = 2;       // channel blocks
constexpr int THREADS = (C_ / CSPLIT) / 2;  // 256 threads, one float2 each
constexpr int STRIDE2 = C_ / 2;             // float2 stride per time step
}

__device__ __forceinline__ float2 ema_step(float2 acc, float2 v) {
    float2 r;
    r.x = fmaf(OMA, acc.x, ALPHA * v.x);
    r.y = fmaf(OMA, acc.y, ALPHA * v.y);
    return r;
}

__global__ __launch_bounds__(THREADS)
void ema_kernel(const float* __restrict__ x, float* __restrict__ y) {
    const int c2 = blockIdx.x * THREADS + threadIdx.x;  // float2 index in channel dim
    const int t0 = blockIdx.y * TCH;
    const int b  = blockIdx.z;

    const float2* __restrict__ xv =
        reinterpret_cast<const float2*>(x) + (size_t)b * T_ * STRIDE2 + c2;
    float2* __restrict__ yv =
        reinterpret_cast<float2*>(y) + (size_t)b * T_ * STRIDE2 + c2;

    int ts = t0 - LW;
    if (ts < 0) ts = 0;

    // Seed. For the first chunk this is exact (y_0 = x_0).
    float2 acc = xv[(size_t)ts * STRIDE2];

    int tstart;
    if (t0 == 0) {
        yv[0] = acc;          // y_0 = x_0 exactly
        tstart = 1;
    } else {
        // Warm-up: t = ts+1 .. t0-1, no stores. 47 iterations; unroll-8 lets
        // ptxas front-batch the loads within each group.
        #pragma unroll 8
        for (int t = ts + 1; t < t0; ++t) {
            acc = ema_step(acc, xv[(size_t)t * STRIDE2]);
        }
        tstart = t0;
    }

    // Main stored region: batch 8 time steps so 8 float2 loads are in flight
    // per thread before the dependent FMA chain consumes them.
    const int tend = t0 + TCH;
    int t = tstart;
    for (; t + 8 <= tend; t += 8) {
        float2 v[8];
        #pragma unroll
        for (int i = 0; i < 8; ++i)
            v[i] = xv[(size_t)(t + i) * STRIDE2];
        #pragma unroll
        for (int i = 0; i < 8; ++i) {
            acc = ema_step(acc, v[i]);
            yv[(size_t)(t + i) * STRIDE2] = acc;
        }
    }
    for (; t < tend; ++t) {
        acc = ema_step(acc, xv[(size_t)t * STRIDE2]);
        yv[(size_t)t * STRIDE2] = acc;
    }
}

extern "C" void kernel_launch(void* const* d_in, const int* in_sizes, int n_in,
                              void* d_out, int out_size) {
    const float* x = (const float*)d_in[0];
    float* y = (float*)d_out;
    (void)n_in; (void)out_size;

    const int batch = in_sizes[0] / (T_ * C_);   // 8 for the reference shape
    dim3 grid(CSPLIT, T_ / TCH, batch);          // (2, 32, 8) = 512 blocks
    ema_kernel<<<grid, THREADS>>>(x, y);
}